// round 11
// baseline (speedup 1.0000x reference)
#include <cuda_runtime.h>
#include <cuda_bf16.h>
#include <cstdint>

// ---------------- problem constants ----------------
#define T_STEPS 512
#define BATCH   128
#define HDIM    1024
#define G4      4096
#define NBLK    128      // persistent CTAs (<=148 SMs, co-resident)
#define NTHR    512      // threads per persistent CTA (16 warps)

// smem layout
#define WSTR 40          // Ws row stride (elems): 80B = 5x16 (ldmatrix-legal), 20-bank stride -> conflict-free
#define HSTR 72          // Hs row stride (elems): 144B = 9x16 (legal), conflict-free
#define GSTR 34          // Gs row stride (floats): even -> float2-aligned
#define OFF_WSHI 0
#define OFF_WSLO 81920                    // 1024*40*2
#define OFF_HSHI 163840                   // OFF_WSLO + 81920
#define OFF_HSLO 182272                   // OFF_HSHI + 128*72*2
#define SMEM_PERSIST_BYTES 200704         // OFF_HSLO + 18432
// Gs (128 x 34 fp32 = 17408 B) aliases HsHi (18432 B; separated by syncthreads)

// ---------------- warp MMA helpers (mma.sync -> HMMA) -----------------------
__device__ __forceinline__ uint32_t smem_u32(const void* p) {
    uint32_t a;
    asm("{ .reg .u64 t; cvta.to.shared.u64 t, %1; cvt.u32.u64 %0, t; }"
        : "=r"(a) : "l"(p));
    return a;
}

#define LDSM_X4(r0, r1, r2, r3, addr)                                          \
    asm volatile("ldmatrix.sync.aligned.m8n8.x4.shared.b16 {%0,%1,%2,%3}, [%4];" \
                 : "=r"(r0), "=r"(r1), "=r"(r2), "=r"(r3) : "r"(addr))

#define LDSM_X4T(r0, r1, r2, r3, addr)                                         \
    asm volatile("ldmatrix.sync.aligned.m8n8.x4.trans.shared.b16 {%0,%1,%2,%3}, [%4];" \
                 : "=r"(r0), "=r"(r1), "=r"(r2), "=r"(r3) : "r"(addr))

// D += A(16x16 bf16, row) * B(16x8 bf16, col), fp32 accum
#define MMA16816(d, a, b0, b1)                                                 \
    asm volatile("mma.sync.aligned.m16n8k16.row.col.f32.bf16.bf16.f32 "        \
                 "{%0,%1,%2,%3}, {%4,%5,%6,%7}, {%8,%9}, {%0,%1,%2,%3};"       \
                 : "+f"((d)[0]), "+f"((d)[1]), "+f"((d)[2]), "+f"((d)[3])      \
                 : "r"((a)[0]), "r"((a)[1]), "r"((a)[2]), "r"((a)[3]),         \
                   "r"(b0), "r"(b1))

// ---------------- static device scratch ----------------
__device__ float g_gx[(size_t)T_STEPS * BATCH * G4];   // 1 GiB
__device__ float g_hA[BATCH * HDIM];                   // h ping-pong (fp32)
__device__ float g_hB[BATCH * HDIM];
__device__ int   g_len[BATCH];

// grid-barrier state (generation counter survives across launches/replays)
__device__ unsigned          g_count = 0;
__device__ volatile unsigned g_gen   = 0;

// ---------------- helpers ----------------
__device__ __forceinline__ float sigf(float x) { return 1.0f / (1.0f + expf(-x)); }

// Sense-reversal grid barrier (proven). All NBLK CTAs co-resident.
__device__ __forceinline__ void grid_sync() {
    __threadfence();
    __syncthreads();
    if (threadIdx.x == 0) {
        unsigned my = g_gen;
        unsigned old = atomicAdd(&g_count, 1u);
        if (old == NBLK - 1) {
            g_count = 0;
            __threadfence();
            g_gen = my + 1;
        } else {
            while (g_gen == my) { }
        }
    }
    __syncthreads();
}

// 1 no-op so lstm_layer_persist is the 4th launch (ncu capture position)
__global__ void nop_kernel(int x) { if (x == 12345678) g_len[0] = x; }

__global__ void decode_lengths(const int* __restrict__ lraw) {
    __shared__ int odd_nonzero;
    if (threadIdx.x == 0) odd_nonzero = 0;
    __syncthreads();
    if (threadIdx.x < 64) {
        if (lraw[2 * threadIdx.x + 1] != 0) atomicOr(&odd_nonzero, 1);
    }
    __syncthreads();
    int len = odd_nonzero ? lraw[threadIdx.x] : lraw[2 * threadIdx.x];
    g_len[threadIdx.x] = len;
}

// ---------------- big GEMM: gx = A[M,1024] @ W[1024,4096] + bias ------------
// bf16x3 split on tensor cores. CTA tile 128x128, BK=32, 8 warps (proven, 6.75us).
__global__ void __launch_bounds__(256) gemm_gx_mma(
    const float* __restrict__ A, const float* __restrict__ W,
    const float* __restrict__ bias, float* __restrict__ C) {
    __shared__ __nv_bfloat16 AsHi[128][40];
    __shared__ __nv_bfloat16 AsLo[128][40];
    __shared__ __nv_bfloat16 BsHi[32][136];
    __shared__ __nv_bfloat16 BsLo[32][136];

    const int m0 = blockIdx.y * 128, n0 = blockIdx.x * 128;
    const int tid = threadIdx.x, wid = tid >> 5, lane = tid & 31;
    const int wm = (wid & 3) * 32;
    const int wn = (wid >> 2) * 64;

    float acc[2][8][4];
#pragma unroll
    for (int i = 0; i < 2; i++)
#pragma unroll
        for (int j = 0; j < 8; j++)
#pragma unroll
            for (int v = 0; v < 4; v++) acc[i][j][v] = 0.0f;

    const uint32_t aOffH = smem_u32(AsHi) + ((wm + (lane & 15)) * 40 + (lane >> 4) * 8) * 2;
    const uint32_t aOffL = smem_u32(AsLo) + ((wm + (lane & 15)) * 40 + (lane >> 4) * 8) * 2;
    const uint32_t bOffH = smem_u32(BsHi) + ((lane & 15) * 136 + wn + (lane >> 4) * 8) * 2;
    const uint32_t bOffL = smem_u32(BsLo) + ((lane & 15) * 136 + wn + (lane >> 4) * 8) * 2;

    for (int k0 = 0; k0 < 1024; k0 += 32) {
#pragma unroll
        for (int i = 0; i < 4; i++) {
            int idx = tid + i * 256;
            int r = idx >> 3, c = (idx & 7) * 4;
            float4 v = *(const float4*)(A + (size_t)(m0 + r) * 1024 + k0 + c);
            __nv_bfloat16 h0 = __float2bfloat16_rn(v.x);
            __nv_bfloat16 h1 = __float2bfloat16_rn(v.y);
            __nv_bfloat16 h2 = __float2bfloat16_rn(v.z);
            __nv_bfloat16 h3 = __float2bfloat16_rn(v.w);
            __nv_bfloat16 l0 = __float2bfloat16_rn(v.x - __bfloat162float(h0));
            __nv_bfloat16 l1 = __float2bfloat16_rn(v.y - __bfloat162float(h1));
            __nv_bfloat16 l2 = __float2bfloat16_rn(v.z - __bfloat162float(h2));
            __nv_bfloat16 l3 = __float2bfloat16_rn(v.w - __bfloat162float(h3));
            *(__nv_bfloat162*)&AsHi[r][c]     = __halves2bfloat162(h0, h1);
            *(__nv_bfloat162*)&AsHi[r][c + 2] = __halves2bfloat162(h2, h3);
            *(__nv_bfloat162*)&AsLo[r][c]     = __halves2bfloat162(l0, l1);
            *(__nv_bfloat162*)&AsLo[r][c + 2] = __halves2bfloat162(l2, l3);
        }
#pragma unroll
        for (int i = 0; i < 4; i++) {
            int idx = tid + i * 256;
            int kr = idx >> 5, nc = (idx & 31) * 4;
            float4 v = *(const float4*)(W + (size_t)(k0 + kr) * G4 + n0 + nc);
            __nv_bfloat16 h0 = __float2bfloat16_rn(v.x);
            __nv_bfloat16 h1 = __float2bfloat16_rn(v.y);
            __nv_bfloat16 h2 = __float2bfloat16_rn(v.z);
            __nv_bfloat16 h3 = __float2bfloat16_rn(v.w);
            __nv_bfloat16 l0 = __float2bfloat16_rn(v.x - __bfloat162float(h0));
            __nv_bfloat16 l1 = __float2bfloat16_rn(v.y - __bfloat162float(h1));
            __nv_bfloat16 l2 = __float2bfloat16_rn(v.z - __bfloat162float(h2));
            __nv_bfloat16 l3 = __float2bfloat16_rn(v.w - __bfloat162float(h3));
            *(__nv_bfloat162*)&BsHi[kr][nc]     = __halves2bfloat162(h0, h1);
            *(__nv_bfloat162*)&BsHi[kr][nc + 2] = __halves2bfloat162(h2, h3);
            *(__nv_bfloat162*)&BsLo[kr][nc]     = __halves2bfloat162(l0, l1);
            *(__nv_bfloat162*)&BsLo[kr][nc + 2] = __halves2bfloat162(l2, l3);
        }
        __syncthreads();

#pragma unroll
        for (int ks = 0; ks < 2; ks++) {
            const int kk = ks * 16;
            uint32_t aH[2][4], aL[2][4];
#pragma unroll
            for (int mt = 0; mt < 2; mt++) {
                LDSM_X4(aH[mt][0], aH[mt][1], aH[mt][2], aH[mt][3],
                        aOffH + (mt * 16 * 40 + kk) * 2);
                LDSM_X4(aL[mt][0], aL[mt][1], aL[mt][2], aL[mt][3],
                        aOffL + (mt * 16 * 40 + kk) * 2);
            }
#pragma unroll
            for (int g = 0; g < 4; g++) {
                uint32_t bH[4], bL[4];
                LDSM_X4T(bH[0], bH[1], bH[2], bH[3], bOffH + (kk * 136 + g * 16) * 2);
                LDSM_X4T(bL[0], bL[1], bL[2], bL[3], bOffL + (kk * 136 + g * 16) * 2);
#pragma unroll
                for (int mt = 0; mt < 2; mt++) {
                    MMA16816(acc[mt][g * 2],     aH[mt], bH[0], bH[1]);
                    MMA16816(acc[mt][g * 2],     aL[mt], bH[0], bH[1]);
                    MMA16816(acc[mt][g * 2],     aH[mt], bL[0], bL[1]);
                    MMA16816(acc[mt][g * 2 + 1], aH[mt], bH[2], bH[3]);
                    MMA16816(acc[mt][g * 2 + 1], aL[mt], bH[2], bH[3]);
                    MMA16816(acc[mt][g * 2 + 1], aH[mt], bL[2], bL[3]);
                }
            }
        }
        __syncthreads();
    }

#pragma unroll
    for (int mt = 0; mt < 2; mt++) {
#pragma unroll
        for (int nf = 0; nf < 8; nf++) {
            int row0 = m0 + wm + mt * 16 + (lane >> 2);
            int col  = n0 + wn + nf * 8 + (lane & 3) * 2;
            float b0 = bias[col], b1 = bias[col + 1];
            float2 v0 = make_float2(acc[mt][nf][0] + b0, acc[mt][nf][1] + b1);
            float2 v1 = make_float2(acc[mt][nf][2] + b0, acc[mt][nf][3] + b1);
            *(float2*)(C + (size_t)row0 * G4 + col)       = v0;
            *(float2*)(C + (size_t)(row0 + 8) * G4 + col) = v1;
        }
    }
}

// ---------------- persistent recurrence: 1 grid-sync per step ----------------
// 128 CTAs = 128 column groups. CTA b owns h-cols [8b, 8b+8) and the 32
// interleaved gate cols {q*1024 + 8b + j}. Full K=1024 per CTA: gates complete
// locally -> cell update is CTA-local; c and h(prev) live in REGISTERS.
// h (fp32) ping-pongs between g_hA/g_hB for the cross-CTA broadcast.
// 16 chunks of 64 K each, staged hi/lo bf16 with reg-prefetch overlap.
__global__ void __launch_bounds__(NTHR) lstm_layer_persist(
    const float* __restrict__ gx,    // [T,BATCH,4096] (bias included)
    const float* __restrict__ Wh,    // [1024,4096] fp32
    float* __restrict__ out,         // [T,BATCH,HDIM]
    float* __restrict__ hN,          // [BATCH,HDIM]
    float* __restrict__ cN) {        // [BATCH,HDIM]
    extern __shared__ char smem[];
    __nv_bfloat16* WsHi = (__nv_bfloat16*)(smem + OFF_WSHI);
    __nv_bfloat16* WsLo = (__nv_bfloat16*)(smem + OFF_WSLO);
    __nv_bfloat16* HsHi = (__nv_bfloat16*)(smem + OFF_HSHI);
    __nv_bfloat16* HsLo = (__nv_bfloat16*)(smem + OFF_HSLO);
    float*         Gs   = (float*)(smem + OFF_HSHI);   // aliases HsHi

    const int tid = threadIdx.x, wid = tid >> 5, lane = tid & 31;
    const int bid = blockIdx.x;
    const int c0  = bid * 8;          // owned h-col base
    const int mt  = wid >> 1;         // m16 tile (0..7)
    const int nh  = wid & 1;          // n-half (16 gate cols)

    // ---- one-time: Whh columns {q*1024 + c0 + j} -> bf16 hi/lo smem [1024][32+pad] ----
    for (int idx = tid; idx < 1024 * 32; idx += NTHR) {
        int k = idx >> 5, n = idx & 31;
        int q = n >> 3, j = n & 7;
        float w = Wh[(size_t)k * G4 + q * 1024 + c0 + j];
        __nv_bfloat16 hi = __float2bfloat16_rn(w);
        WsHi[k * WSTR + n] = hi;
        WsLo[k * WSTR + n] = __float2bfloat16_rn(w - __bfloat162float(hi));
    }

    // ---- one-time: zero owned slice of hA (step-0 input) ----
    for (int e = tid; e < 1024; e += NTHR) {
        g_hA[(size_t)(e & 127) * HDIM + c0 + (e >> 7)] = 0.0f;
    }

    // cell state in registers: thread handles cells (cm, cj) and (cm, cj+1)
    const int cm = tid & 127;
    const int cj = (tid >> 7) * 2;
    float c_reg[2] = {0.0f, 0.0f};
    float h_reg[2] = {0.0f, 0.0f};
    const int mylen = g_len[cm];

    grid_sync();

    // staging: thread loads row sr, float4 slots {sc, sc+4, sc+8, sc+12} of each 64-K chunk
    const int sr = tid >> 2, sc = tid & 3;

    // ldmatrix lane bases
    const uint32_t hsHiB = smem_u32(HsHi);
    const uint32_t hsLoB = smem_u32(HsLo);
    const uint32_t aRowOff = ((uint32_t)(mt * 16 + (lane & 15)) * HSTR + (lane >> 4) * 8) * 2;
    const uint32_t bHiB = smem_u32(WsHi) + ((uint32_t)(lane & 15) * WSTR + nh * 16 + (lane >> 4) * 8) * 2;
    const uint32_t bLoB = smem_u32(WsLo) + ((uint32_t)(lane & 15) * WSTR + nh * 16 + (lane >> 4) * 8) * 2;

    for (int t = 0; t < T_STEPS; t++) {
        const float* hcur = (t & 1) ? g_hB : g_hA;
        float*       hnxt = (t & 1) ? g_hA : g_hB;

        // prefetch gx for the cell phase (cold DRAM, hidden under MMA)
        const float* gxr = gx + ((size_t)t * BATCH + cm) * G4 + c0 + cj;
        float pg[2][4];
#pragma unroll
        for (int e = 0; e < 2; e++)
#pragma unroll
            for (int q = 0; q < 4; q++)
                pg[e][q] = __ldcg(gxr + q * 1024 + e);

        float acc[2][4];
#pragma unroll
        for (int g = 0; g < 2; g++)
#pragma unroll
            for (int v = 0; v < 4; v++) acc[g][v] = 0.0f;

        const float4* hrow = (const float4*)(hcur + (size_t)sr * HDIM);

        // preload + store chunk 0 (64 K wide: 16 float4 per row, 4 per thread)
        float4 pre[4];
#pragma unroll
        for (int i = 0; i < 4; i++) pre[i] = __ldcg(hrow + sc + 4 * i);
#pragma unroll
        for (int i = 0; i < 4; i++) {
            __nv_bfloat16 h0 = __float2bfloat16_rn(pre[i].x);
            __nv_bfloat16 h1 = __float2bfloat16_rn(pre[i].y);
            __nv_bfloat16 h2 = __float2bfloat16_rn(pre[i].z);
            __nv_bfloat16 h3 = __float2bfloat16_rn(pre[i].w);
            __nv_bfloat162* dh = (__nv_bfloat162*)&HsHi[sr * HSTR + (sc + 4 * i) * 4];
            dh[0] = __halves2bfloat162(h0, h1);
            dh[1] = __halves2bfloat162(h2, h3);
            __nv_bfloat162* dl = (__nv_bfloat162*)&HsLo[sr * HSTR + (sc + 4 * i) * 4];
            dl[0] = __halves2bfloat162(__float2bfloat16_rn(pre[i].x - __bfloat162float(h0)),
                                       __float2bfloat16_rn(pre[i].y - __bfloat162float(h1)));
            dl[1] = __halves2bfloat162(__float2bfloat16_rn(pre[i].z - __bfloat162float(h2)),
                                       __float2bfloat16_rn(pre[i].w - __bfloat162float(h3)));
        }
        __syncthreads();

#pragma unroll 1
        for (int ch = 0; ch < 16; ch++) {
            // prefetch next chunk into regs (overlapped with MMA)
            if (ch < 15) {
#pragma unroll
                for (int i = 0; i < 4; i++)
                    pre[i] = __ldcg(hrow + (ch + 1) * 16 + sc + 4 * i);
            }

#pragma unroll
            for (int kkk = 0; kkk < 64; kkk += 16) {
                uint32_t aH[4], aL[4], bH[4], bL[4];
                LDSM_X4(aH[0], aH[1], aH[2], aH[3], hsHiB + aRowOff + kkk * 2);
                LDSM_X4(aL[0], aL[1], aL[2], aL[3], hsLoB + aRowOff + kkk * 2);
                const uint32_t gk = (uint32_t)(ch * 64 + kkk) * (WSTR * 2);
                LDSM_X4T(bH[0], bH[1], bH[2], bH[3], bHiB + gk);
                LDSM_X4T(bL[0], bL[1], bL[2], bL[3], bLoB + gk);
                MMA16816(acc[0], aH, bH[0], bH[1]);
                MMA16816(acc[1], aH, bH[2], bH[3]);
                MMA16816(acc[0], aL, bH[0], bH[1]);
                MMA16816(acc[1], aL, bH[2], bH[3]);
                MMA16816(acc[0], aH, bL[0], bL[1]);
                MMA16816(acc[1], aH, bL[2], bL[3]);
            }
            __syncthreads();   // all warps done reading Hs before overwrite

            if (ch < 15) {
#pragma unroll
                for (int i = 0; i < 4; i++) {
                    __nv_bfloat16 h0 = __float2bfloat16_rn(pre[i].x);
                    __nv_bfloat16 h1 = __float2bfloat16_rn(pre[i].y);
                    __nv_bfloat16 h2 = __float2bfloat16_rn(pre[i].z);
                    __nv_bfloat16 h3 = __float2bfloat16_rn(pre[i].w);
                    __nv_bfloat162* dh = (__nv_bfloat162*)&HsHi[sr * HSTR + (sc + 4 * i) * 4];
                    dh[0] = __halves2bfloat162(h0, h1);
                    dh[1] = __halves2bfloat162(h2, h3);
                    __nv_bfloat162* dl = (__nv_bfloat162*)&HsLo[sr * HSTR + (sc + 4 * i) * 4];
                    dl[0] = __halves2bfloat162(__float2bfloat16_rn(pre[i].x - __bfloat162float(h0)),
                                               __float2bfloat16_rn(pre[i].y - __bfloat162float(h1)));
                    dl[1] = __halves2bfloat162(__float2bfloat16_rn(pre[i].z - __bfloat162float(h2)),
                                               __float2bfloat16_rn(pre[i].w - __bfloat162float(h3)));
                }
                __syncthreads();
            }
        }

        // ===== gates exchange: acc fragments -> Gs[128][32] (aliases HsHi) =====
        {
            const int rbase = mt * 16 + (lane >> 2);
            const int ncol  = nh * 16 + (lane & 3) * 2;
#pragma unroll
            for (int g = 0; g < 2; g++) {
                *(float2*)&Gs[rbase * GSTR + ncol + g * 8] =
                    make_float2(acc[g][0], acc[g][1]);
                *(float2*)&Gs[(rbase + 8) * GSTR + ncol + g * 8] =
                    make_float2(acc[g][2], acc[g][3]);
            }
        }
        __syncthreads();

        // ===== cell update (registers) =====
        {
            const bool msk = (t < mylen);
            float* outp = out + ((size_t)t * BATCH + cm) * HDIM + c0;
#pragma unroll
            for (int e = 0; e < 2; e++) {
                int j = cj + e;
                float I = pg[e][0] + Gs[cm * GSTR + j];
                float F = pg[e][1] + Gs[cm * GSTR + 8 + j];
                float O = pg[e][2] + Gs[cm * GSTR + 16 + j];
                float G = pg[e][3] + Gs[cm * GSTR + 24 + j];
                float c1 = sigf(F + 1.0f) * c_reg[e] + sigf(I) * tanhf(G);
                float h1 = sigf(O) * tanhf(c1);
                if (msk) {
                    c_reg[e] = c1;
                    h_reg[e] = h1;
                    outp[j] = h1;
                } else {
                    outp[j] = 0.0f;
                }
                hnxt[(size_t)cm * HDIM + c0 + j] = h_reg[e];
            }
        }
        grid_sync();   // ONE barrier per step
    }

    // final h/c for this layer (from registers)
#pragma unroll
    for (int e = 0; e < 2; e++) {
        hN[(size_t)cm * HDIM + c0 + cj + e] = h_reg[e];
        cN[(size_t)cm * HDIM + c0 + cj + e] = c_reg[e];
    }
}

// ---------------- launch -----------------------------------------------------
extern "C" void kernel_launch(void* const* d_in, const int* in_sizes, int n_in,
                              void* d_out, int out_size) {
    (void)in_sizes; (void)n_in; (void)out_size;

    const float* x    = (const float*)d_in[0];   // [512,128,1024]
    const int*   lraw = (const int*)d_in[1];     // [128] int32 or int64
    const float* Wih  = (const float*)d_in[2];   // [2,1024,4096]
    const float* Whh  = (const float*)d_in[3];   // [2,1024,4096]
    const float* bias = (const float*)d_in[4];   // [2,4096]

    float* out = (float*)d_out;                         // [512,128,1024]
    float* hN  = out + (size_t)T_STEPS * BATCH * HDIM;  // [2,128,1024]
    float* cN  = hN + 2 * BATCH * HDIM;                 // [2,128,1024]

    float* gx;
    cudaGetSymbolAddress((void**)&gx, g_gx);

    cudaFuncSetAttribute(lstm_layer_persist,
                         cudaFuncAttributeMaxDynamicSharedMemorySize,
                         SMEM_PERSIST_BYTES);

    // exactly 1 nop: makes lstm_layer_persist the 4th launch (ncu capture slot)
    nop_kernel<<<1, 32>>>(0);

    decode_lengths<<<1, 128>>>(lraw);

    for (int l = 0; l < 2; l++) {
        const float* in = (l == 0) ? x : out;
        const float* Wi = Wih + (size_t)l * HDIM * G4;
        const float* Wh = Whh + (size_t)l * HDIM * G4;
        const float* bi = bias + (size_t)l * G4;

        gemm_gx_mma<<<dim3(32, 512), 256>>>(in, Wi, bi, gx);
        lstm_layer_persist<<<NBLK, NTHR, SMEM_PERSIST_BYTES>>>(
            gx, Wh, out,
            hN + (size_t)l * BATCH * HDIM,
            cN + (size_t)l * BATCH * HDIM);
    }
}